// round 6
// baseline (speedup 1.0000x reference)
#include <cuda_runtime.h>
#include <math.h>

#define NN 50000
#define H 256
#define EMAX 800000
#define NH (NN * H)

// ---------------- device scratch ----------------
__device__ int   g_is64;
__device__ int   g_deg[NN];
__device__ float g_dinv[NN];
__device__ int   g_rowptr[NN + 1];
__device__ int   g_cursor[NN];
__device__ int   g_csrc[EMAX];
__device__ float g_bufA[NH];   // holds h = relu(conv1 aggregate)

// edge index loader: j-th element of edge buffer under detected dtype
__device__ __forceinline__ int load_idx(const void* ei, long long j, int is64) {
    if (is64) return (int)((const long long*)ei)[j];
    return ((const int*)ei)[j];
}

// ---------------- dtype detection: int64 vs int32 edge_index ----------------
// View buffer as int32. For int64 data with values in [0, 2^31), every odd
// word is 0. For int32 index data (~U[0,50000)), odd words are src/dst values;
// 2048 samples all being zero has probability ~0.
__global__ void detect_kernel(const int* __restrict__ w, int E) {
    __shared__ int nz;
    if (threadIdx.x == 0) nz = 0;
    __syncthreads();
    if (E > 0) {
        for (int j = threadIdx.x; j < 2048; j += blockDim.x) {
            long long idx = ((long long)j * E) / 2048;   // spread samples over [0,E)
            if (w[2 * idx + 1] != 0) atomicOr(&nz, 1);
        }
    }
    __syncthreads();
    if (threadIdx.x == 0) g_is64 = (nz == 0) ? 1 : 0;
}

// ---------------- graph preprocessing ----------------
__global__ void init_kernel() {
    int i = blockIdx.x * blockDim.x + threadIdx.x;
    if (i < NN) { g_deg[i] = 1; g_cursor[i] = 0; }   // 1 = self loop
}

__global__ void count_kernel(const void* __restrict__ ei, int E) {
    int e = blockIdx.x * blockDim.x + threadIdx.x;
    if (e < E) {
        int is64 = g_is64;
        int d = load_idx(ei, (long long)E + e, is64);   // dst
        if ((unsigned)d < (unsigned)NN) atomicAdd(&g_deg[d], 1);
    }
}

__global__ void dinv_kernel() {
    int i = blockIdx.x * blockDim.x + threadIdx.x;
    if (i < NN) g_dinv[i] = rsqrtf((float)g_deg[i]);
}

// exclusive scan of (deg-1) -> rowptr. single block, 1024 threads.
__global__ void scan_kernel() {
    __shared__ int sums[1024];
    int t = threadIdx.x;
    const int chunk = (NN + 1023) / 1024;  // 49
    int start = t * chunk;
    int end = start + chunk; if (end > NN) end = NN;
    int s = 0;
    for (int i = start; i < end; i++) s += g_deg[i] - 1;
    sums[t] = s;
    __syncthreads();
    if (t == 0) {
        int run = 0;
        for (int i = 0; i < 1024; i++) { int v = sums[i]; sums[i] = run; run += v; }
    }
    __syncthreads();
    int run = sums[t];
    for (int i = start; i < end; i++) {
        run += g_deg[i] - 1;
        g_rowptr[i + 1] = run;
    }
    if (t == 0) g_rowptr[0] = 0;
}

__global__ void scatter_kernel(const void* __restrict__ ei, int E) {
    int e = blockIdx.x * blockDim.x + threadIdx.x;
    if (e < E) {
        int is64 = g_is64;
        int s = load_idx(ei, e, is64);                  // src
        int d = load_idx(ei, (long long)E + e, is64);   // dst
        if ((unsigned)d < (unsigned)NN && (unsigned)s < (unsigned)NN) {
            int pos = atomicAdd(&g_cursor[d], 1);
            int slot = g_rowptr[d] + pos;
            if (slot < EMAX) g_csrc[slot] = s;
        }
    }
}

// ---------------- GEMM: C[M,256] = A1@B1 (+ A2@B2), fp32 ----------------
// 128x128 tile, 256 threads, 8x8 per thread, BK=16.
// a1_scratch != 0 -> A1 = g_bufA (device scratch)
// mode 0: C = acc
// mode 1 (gate): g = acc + bias1[n] + bias2[n]; a = sigmoid(g);
//                C = a*A1[m,n] + (1-a)*A2[m,n]   (A1 = h_t, A2 = prev)
__global__ __launch_bounds__(256) void gemm_kernel(
    const float* __restrict__ A1, const float* __restrict__ B1,
    const float* __restrict__ A2, const float* __restrict__ B2,
    float* __restrict__ C,
    const float* __restrict__ bias1, const float* __restrict__ bias2,
    int M, int mode, int a1_scratch)
{
    __shared__ __align__(16) float As[128][20];
    __shared__ __align__(16) float Bs[16][128];

    if (a1_scratch) A1 = g_bufA;

    int tid = threadIdx.x;
    int tr = tid >> 4;          // 0..15 -> 8 rows each
    int tc = tid & 15;          // 0..15 -> 8 cols each
    int m0 = blockIdx.y * 128;
    int n0 = blockIdx.x * 128;

    float acc[8][8];
#pragma unroll
    for (int i = 0; i < 8; i++)
#pragma unroll
        for (int j = 0; j < 8; j++) acc[i][j] = 0.f;

    for (int pair = 0; pair < 2; pair++) {
        const float* A = pair ? A2 : A1;
        const float* B = pair ? B2 : B1;
        if (A == nullptr || B == nullptr) break;

        for (int k0 = 0; k0 < H; k0 += 16) {
#pragma unroll
            for (int l = 0; l < 2; l++) {
                int f = tid * 2 + l;
                int r = f >> 2;
                int kq = (f & 3) * 4;
                int m = m0 + r;
                float4 v = make_float4(0.f, 0.f, 0.f, 0.f);
                if (m < M) v = *(const float4*)(A + (size_t)m * H + k0 + kq);
                *(float4*)&As[r][kq] = v;
            }
#pragma unroll
            for (int l = 0; l < 2; l++) {
                int f = tid * 2 + l;
                int kk = f >> 5;
                int cq = (f & 31) * 4;
                *(float4*)&Bs[kk][cq] = *(const float4*)(B + (size_t)(k0 + kk) * H + n0 + cq);
            }
            __syncthreads();

#pragma unroll
            for (int kk = 0; kk < 16; kk++) {
                float a[8], b[8];
#pragma unroll
                for (int i = 0; i < 8; i++) a[i] = As[tr * 8 + i][kk];
                float4 b0 = *(float4*)&Bs[kk][tc * 8];
                float4 b1 = *(float4*)&Bs[kk][tc * 8 + 4];
                b[0] = b0.x; b[1] = b0.y; b[2] = b0.z; b[3] = b0.w;
                b[4] = b1.x; b[5] = b1.y; b[6] = b1.z; b[7] = b1.w;
#pragma unroll
                for (int i = 0; i < 8; i++)
#pragma unroll
                    for (int j = 0; j < 8; j++)
                        acc[i][j] = fmaf(a[i], b[j], acc[i][j]);
            }
            __syncthreads();
        }
    }

    if (mode == 0) {
#pragma unroll
        for (int i = 0; i < 8; i++) {
            int m = m0 + tr * 8 + i;
            if (m < M) {
                float4 v0 = make_float4(acc[i][0], acc[i][1], acc[i][2], acc[i][3]);
                float4 v1 = make_float4(acc[i][4], acc[i][5], acc[i][6], acc[i][7]);
                *(float4*)(C + (size_t)m * H + n0 + tc * 8) = v0;
                *(float4*)(C + (size_t)m * H + n0 + tc * 8 + 4) = v1;
            }
        }
    } else {
        float bsum[8];
#pragma unroll
        for (int j = 0; j < 8; j++) {
            int n = n0 + tc * 8 + j;
            bsum[j] = bias1[n] + bias2[n];
        }
#pragma unroll
        for (int i = 0; i < 8; i++) {
            int m = m0 + tr * 8 + i;
            if (m < M) {
                float o[8];
#pragma unroll
                for (int j = 0; j < 8; j++) {
                    int n = n0 + tc * 8 + j;
                    float gv = acc[i][j] + bsum[j];
                    float a = 1.f / (1.f + __expf(-gv));
                    float ht = A1[(size_t)m * H + n];
                    float pv = A2[(size_t)m * H + n];
                    o[j] = fmaf(a, ht - pv, pv);
                }
                float4 v0 = make_float4(o[0], o[1], o[2], o[3]);
                float4 v1 = make_float4(o[4], o[5], o[6], o[7]);
                *(float4*)(C + (size_t)m * H + n0 + tc * 8) = v0;
                *(float4*)(C + (size_t)m * H + n0 + tc * 8 + 4) = v1;
            }
        }
    }
}

// ---------------- aggregation: one warp per node ----------------
// out_scratch != 0 -> out = g_bufA; else out = outp
__global__ void agg_kernel(const float* __restrict__ hin, float* outp,
                           const float* __restrict__ bias,
                           int do_relu, int out_scratch)
{
    int warp = (blockIdx.x * blockDim.x + threadIdx.x) >> 5;
    int lane = threadIdx.x & 31;
    if (warp >= NN) return;
    int node = warp;

    float* out = out_scratch ? g_bufA : outp;

    float di = g_dinv[node];
    const float4* selfrow = (const float4*)(hin + (size_t)node * H);
    float ws = di * di;
    float4 v0 = selfrow[lane * 2];
    float4 v1 = selfrow[lane * 2 + 1];
    float a0 = ws * v0.x, a1 = ws * v0.y, a2 = ws * v0.z, a3 = ws * v0.w;
    float a4 = ws * v1.x, a5 = ws * v1.y, a6 = ws * v1.z, a7 = ws * v1.w;

    int beg = g_rowptr[node], end = g_rowptr[node + 1];
    for (int e = beg; e < end; e++) {
        int s = g_csrc[e];
        float w = g_dinv[s] * di;
        const float4* r = (const float4*)(hin + (size_t)s * H);
        float4 u0 = r[lane * 2];
        float4 u1 = r[lane * 2 + 1];
        a0 = fmaf(w, u0.x, a0); a1 = fmaf(w, u0.y, a1);
        a2 = fmaf(w, u0.z, a2); a3 = fmaf(w, u0.w, a3);
        a4 = fmaf(w, u1.x, a4); a5 = fmaf(w, u1.y, a5);
        a6 = fmaf(w, u1.z, a6); a7 = fmaf(w, u1.w, a7);
    }

    const float4* bp = (const float4*)bias;
    float4 b0 = bp[lane * 2];
    float4 b1 = bp[lane * 2 + 1];
    a0 += b0.x; a1 += b0.y; a2 += b0.z; a3 += b0.w;
    a4 += b1.x; a5 += b1.y; a6 += b1.z; a7 += b1.w;
    if (do_relu) {
        a0 = fmaxf(a0, 0.f); a1 = fmaxf(a1, 0.f); a2 = fmaxf(a2, 0.f); a3 = fmaxf(a3, 0.f);
        a4 = fmaxf(a4, 0.f); a5 = fmaxf(a5, 0.f); a6 = fmaxf(a6, 0.f); a7 = fmaxf(a7, 0.f);
    }
    float4* op = (float4*)(out + (size_t)node * H);
    op[lane * 2]     = make_float4(a0, a1, a2, a3);
    op[lane * 2 + 1] = make_float4(a4, a5, a6, a7);
}

// ---------------- launcher ----------------
extern "C" void kernel_launch(void* const* d_in, const int* in_sizes, int n_in,
                              void* d_out, int out_size)
{
    const float* x    = (const float*)d_in[0];
    const void*  ei   = d_in[1];                 // int32 or int64, detected on device
    const float* prev = (const float*)d_in[2];
    const float* W1   = (const float*)d_in[3];
    const float* b1   = (const float*)d_in[4];
    const float* W2   = (const float*)d_in[5];
    const float* b2   = (const float*)d_in[6];
    const float* gWw  = (const float*)d_in[7];
    const float* gWb  = (const float*)d_in[8];
    const float* gUw  = (const float*)d_in[9];
    const float* gUb  = (const float*)d_in[10];

    int E = in_sizes[1] / 2;

    float* out_lo = (float*)d_out;        // final h_tilde; scratch before that
    float* h_t    = out_lo + NH;          // final h_t (second tuple element)

    // graph preprocessing
    detect_kernel<<<1, 256>>>((const int*)ei, E);
    init_kernel<<<(NN + 255) / 256, 256>>>();
    count_kernel<<<(E + 255) / 256, 256>>>(ei, E);
    dinv_kernel<<<(NN + 255) / 256, 256>>>();
    scan_kernel<<<1, 1024>>>();
    scatter_kernel<<<(E + 255) / 256, 256>>>(ei, E);

    dim3 ggrid(H / 128, (NN + 127) / 128);

    // conv1: h0 = x@W1 -> out_lo (scratch); h = relu(agg(h0)+b1) -> g_bufA
    gemm_kernel<<<ggrid, 256>>>(x, W1, nullptr, nullptr, out_lo,
                                nullptr, nullptr, NN, 0, 0);
    agg_kernel<<<(NN * 32 + 255) / 256, 256>>>(out_lo, nullptr, b1, 1, 1);

    // conv2: t0 = h@W2 -> out_lo (scratch); h_t = agg(t0)+b2 -> out_hi
    gemm_kernel<<<ggrid, 256>>>(nullptr, W2, nullptr, nullptr, out_lo,
                                nullptr, nullptr, NN, 0, 1);
    agg_kernel<<<(NN * 32 + 255) / 256, 256>>>(out_lo, h_t, b2, 0, 0);

    // gate (fused): acc = h_t@gWw + prev@gUw; out_lo = sig(acc+gWb+gUb)*h_t + (1-sig)*prev
    gemm_kernel<<<ggrid, 256>>>(h_t, gWw, prev, gUw, out_lo,
                                gWb, gUb, NN, 1, 0);
}

// round 9
// speedup vs baseline: 1.8119x; 1.8119x over previous
#include <cuda_runtime.h>
#include <cuda_bf16.h>
#include <math.h>
#include <stdint.h>

#define NN 50000
#define H 256
#define EMAX 800000
#define NH (NN * H)

#define TILEM 128
#define GM ((NN + TILEM - 1) / TILEM)   // 391

// ---------------- device scratch ----------------
__device__ int   g_is64;
__device__ int   g_deg[NN];
__device__ float g_dinv[NN];
__device__ int   g_rowptr[NN + 1];
__device__ int   g_cursor[NN];
__device__ int   g_csrc[EMAX];
__device__ float g_bufA[NH];                        // h = relu(conv1 agg)
__device__ __align__(16) __nv_bfloat16 g_Whi[4][65536];  // W^T bf16-hi, [n][k]
__device__ __align__(16) __nv_bfloat16 g_Wlo[4][65536];  // W^T bf16-lo, [n][k]

// mma.sync bf16: D = A(16x16,row) * B(16x8,col) + D, fp32 acc. sm_80+ baseline.
#define MMA_BF16(c, a, b) \
    asm volatile("mma.sync.aligned.m16n8k16.row.col.f32.bf16.bf16.f32 " \
        "{%0,%1,%2,%3}, {%4,%5,%6,%7}, {%8,%9}, {%0,%1,%2,%3};" \
        : "+f"((c)[0]), "+f"((c)[1]), "+f"((c)[2]), "+f"((c)[3]) \
        : "r"((a)[0]), "r"((a)[1]), "r"((a)[2]), "r"((a)[3]), \
          "r"((b)[0]), "r"((b)[1]))

// ---------------- edge dtype detection + graph preprocessing ----------------
__device__ __forceinline__ int load_idx(const void* ei, long long j, int is64) {
    if (is64) return (int)((const long long*)ei)[j];
    return ((const int*)ei)[j];
}

__global__ void detect_kernel(const int* __restrict__ w, int E) {
    __shared__ int nz;
    if (threadIdx.x == 0) nz = 0;
    __syncthreads();
    if (E > 0) {
        for (int j = threadIdx.x; j < 2048; j += blockDim.x) {
            long long idx = ((long long)j * E) / 2048;
            if (w[2 * idx + 1] != 0) atomicOr(&nz, 1);
        }
    }
    __syncthreads();
    if (threadIdx.x == 0) g_is64 = (nz == 0) ? 1 : 0;
}

__global__ void init_kernel() {
    int i = blockIdx.x * blockDim.x + threadIdx.x;
    if (i < NN) { g_deg[i] = 1; g_cursor[i] = 0; }
}

__global__ void count_kernel(const void* __restrict__ ei, int E) {
    int e = blockIdx.x * blockDim.x + threadIdx.x;
    if (e < E) {
        int d = load_idx(ei, (long long)E + e, g_is64);
        if ((unsigned)d < (unsigned)NN) atomicAdd(&g_deg[d], 1);
    }
}

__global__ void dinv_kernel() {
    int i = blockIdx.x * blockDim.x + threadIdx.x;
    if (i < NN) g_dinv[i] = rsqrtf((float)g_deg[i]);
}

__global__ void scan_kernel() {
    __shared__ int sums[1024];
    int t = threadIdx.x;
    const int chunk = (NN + 1023) / 1024;
    int start = t * chunk;
    int end = start + chunk; if (end > NN) end = NN;
    int s = 0;
    for (int i = start; i < end; i++) s += g_deg[i] - 1;
    sums[t] = s;
    __syncthreads();
    if (t == 0) {
        int run = 0;
        for (int i = 0; i < 1024; i++) { int v = sums[i]; sums[i] = run; run += v; }
    }
    __syncthreads();
    int run = sums[t];
    for (int i = start; i < end; i++) {
        run += g_deg[i] - 1;
        g_rowptr[i + 1] = run;
    }
    if (t == 0) g_rowptr[0] = 0;
}

__global__ void scatter_kernel(const void* __restrict__ ei, int E) {
    int e = blockIdx.x * blockDim.x + threadIdx.x;
    if (e < E) {
        int is64 = g_is64;
        int s = load_idx(ei, e, is64);
        int d = load_idx(ei, (long long)E + e, is64);
        if ((unsigned)d < (unsigned)NN && (unsigned)s < (unsigned)NN) {
            int pos = atomicAdd(&g_cursor[d], 1);
            int slot = g_rowptr[d] + pos;
            if (slot < EMAX) g_csrc[slot] = s;
        }
    }
}

// ---------------- weight prep: W -> W^T bf16 hi/lo images ([n][k]) ----------
__global__ void prep_kernel(const float* __restrict__ W1, const float* __restrict__ W2,
                            const float* __restrict__ W3, const float* __restrict__ W4) {
    int idx = blockIdx.x * blockDim.x + threadIdx.x;
    if (idx >= 4 * 65536) return;
    int mat = idx >> 16;
    int rem = idx & 65535;
    int k = rem >> 8;      // input dim
    int n = rem & 255;     // output dim
    const float* W = (mat == 0) ? W1 : (mat == 1) ? W2 : (mat == 2) ? W3 : W4;
    float v = W[k * 256 + n];
    __nv_bfloat16 hi = __float2bfloat16(v);
    __nv_bfloat16 lo = __float2bfloat16(v - __bfloat162float(hi));
    g_Whi[mat][n * 256 + k] = hi;
    g_Wlo[mat][n * 256 + k] = lo;
}

// ---------------- tensor GEMM via mma.sync (split bf16, 3 terms) ------------
// C[M,256] = sum_pairs A_p @ W_p.  CTA tile 128(m) x 128(n), BK=32, 8 warps.
// mode 0: C = acc.  mode 1 (gate): a = sigmoid(acc + b1[n] + b2[n]);
//                    C = a*A1 + (1-a)*A2  (A1=h_t, A2=prev)
__global__ __launch_bounds__(256) void tgemm_kernel(
    const float* __restrict__ A1, const float* __restrict__ A2,
    float* __restrict__ C,
    const float* __restrict__ bias1, const float* __restrict__ bias2,
    int M, int mode, int npair, int mat1, int mat2, int a1_scratch)
{
    __shared__ uint32_t sAhi[128][20], sAlo[128][20];
    __shared__ uint32_t sBhi[128][20], sBlo[128][20];

    if (a1_scratch) A1 = g_bufA;

    int tid = threadIdx.x;
    int lane = tid & 31, wid = tid >> 5;
    int g = lane >> 2, tig = lane & 3;
    int warp_m = wid & 3;        // 4 warps over 128 m-rows (32 each)
    int warp_n = wid >> 2;       // 2 warps over 128 n-cols (64 each)
    int m0 = blockIdx.y * TILEM;
    int n0 = blockIdx.x * 128;

    float acc[16][4];
#pragma unroll
    for (int i = 0; i < 16; i++)
#pragma unroll
        for (int j = 0; j < 4; j++) acc[i][j] = 0.f;

    int r = tid >> 1, half = tid & 1;    // A stage-load assignment
    int m_ld = m0 + r;

    for (int pair = 0; pair < npair; pair++) {
        const float* A = pair ? A2 : A1;
        const __nv_bfloat16* Whi = g_Whi[pair ? mat2 : mat1];
        const __nv_bfloat16* Wlo = g_Wlo[pair ? mat2 : mat1];

        for (int k0 = 0; k0 < H; k0 += 32) {
            __syncthreads();   // previous stage fully consumed
            // A stage: 128 rows x 32 k fp32 -> bf16 hi/lo
            {
                const float* arow = A + (size_t)m_ld * H + k0 + half * 16;
#pragma unroll
                for (int w = 0; w < 8; w++) {
                    float2 v = (m_ld < M) ? *(const float2*)(arow + w * 2)
                                          : make_float2(0.f, 0.f);
                    __nv_bfloat16 h0 = __float2bfloat16(v.x);
                    __nv_bfloat16 h1 = __float2bfloat16(v.y);
                    __nv_bfloat16 l0 = __float2bfloat16(v.x - __bfloat162float(h0));
                    __nv_bfloat16 l1 = __float2bfloat16(v.y - __bfloat162float(h1));
                    sAhi[r][half * 8 + w] =
                        (uint32_t)__bfloat16_as_ushort(h0) | ((uint32_t)__bfloat16_as_ushort(h1) << 16);
                    sAlo[r][half * 8 + w] =
                        (uint32_t)__bfloat16_as_ushort(l0) | ((uint32_t)__bfloat16_as_ushort(l1) << 16);
                }
            }
            // B stage: rows n0..n0+127 of W^T, 32 k bf16 (hi+lo), raw copies
#pragma unroll
            for (int l = 0; l < 2; l++) {
                int i = tid * 2 + l;
                int nrow = i >> 2, seg = i & 3;
                size_t off = (size_t)(n0 + nrow) * H + k0 + seg * 8;
                *(uint4*)&sBhi[nrow][seg * 4] = *(const uint4*)(Whi + off);
                *(uint4*)&sBlo[nrow][seg * 4] = *(const uint4*)(Wlo + off);
            }
            __syncthreads();

            // compute: 2 k16 steps
#pragma unroll
            for (int ks = 0; ks < 2; ks++) {
                int kw = ks * 8;
                uint32_t ah[2][4], al[2][4], bh[8][2], bl[8][2];
#pragma unroll
                for (int mt = 0; mt < 2; mt++) {
                    int r0 = warp_m * 32 + mt * 16 + g;
                    ah[mt][0] = sAhi[r0][kw + tig];
                    ah[mt][1] = sAhi[r0 + 8][kw + tig];
                    ah[mt][2] = sAhi[r0][kw + tig + 4];
                    ah[mt][3] = sAhi[r0 + 8][kw + tig + 4];
                    al[mt][0] = sAlo[r0][kw + tig];
                    al[mt][1] = sAlo[r0 + 8][kw + tig];
                    al[mt][2] = sAlo[r0][kw + tig + 4];
                    al[mt][3] = sAlo[r0 + 8][kw + tig + 4];
                }
#pragma unroll
                for (int nt = 0; nt < 8; nt++) {
                    int n = warp_n * 64 + nt * 8 + g;
                    bh[nt][0] = sBhi[n][kw + tig];
                    bh[nt][1] = sBhi[n][kw + tig + 4];
                    bl[nt][0] = sBlo[n][kw + tig];
                    bl[nt][1] = sBlo[n][kw + tig + 4];
                }
#pragma unroll
                for (int mt = 0; mt < 2; mt++)
#pragma unroll
                    for (int nt = 0; nt < 8; nt++) {
                        float* c = acc[mt * 8 + nt];
                        MMA_BF16(c, ah[mt], bh[nt]);
                        MMA_BF16(c, al[mt], bh[nt]);
                        MMA_BF16(c, ah[mt], bl[nt]);
                    }
            }
        }
    }

    // epilogue
#pragma unroll
    for (int mt = 0; mt < 2; mt++) {
        int r0 = m0 + warp_m * 32 + mt * 16 + g;
#pragma unroll
        for (int nt = 0; nt < 8; nt++) {
            int ncol = n0 + warp_n * 64 + nt * 8 + tig * 2;
            float* c = acc[mt * 8 + nt];
            if (mode == 0) {
                if (r0 < M)
                    *(float2*)(C + (size_t)r0 * H + ncol) = make_float2(c[0], c[1]);
                if (r0 + 8 < M)
                    *(float2*)(C + (size_t)(r0 + 8) * H + ncol) = make_float2(c[2], c[3]);
            } else {
                float bs0 = bias1[ncol] + bias2[ncol];
                float bs1 = bias1[ncol + 1] + bias2[ncol + 1];
#pragma unroll
                for (int rr = 0; rr < 2; rr++) {
                    int m = r0 + rr * 8;
                    if (m < M) {
                        float2 ht = *(const float2*)(A1 + (size_t)m * H + ncol);
                        float2 pv = *(const float2*)(A2 + (size_t)m * H + ncol);
                        float g0 = c[rr * 2 + 0] + bs0;
                        float g1 = c[rr * 2 + 1] + bs1;
                        float a0 = 1.f / (1.f + __expf(-g0));
                        float a1 = 1.f / (1.f + __expf(-g1));
                        float2 o;
                        o.x = fmaf(a0, ht.x - pv.x, pv.x);
                        o.y = fmaf(a1, ht.y - pv.y, pv.y);
                        *(float2*)(C + (size_t)m * H + ncol) = o;
                    }
                }
            }
        }
    }
}

// ---------------- aggregation: one warp per node ----------------
__global__ void agg_kernel(const float* __restrict__ hin, float* outp,
                           const float* __restrict__ bias,
                           int do_relu, int out_scratch)
{
    int warp = (blockIdx.x * blockDim.x + threadIdx.x) >> 5;
    int lane = threadIdx.x & 31;
    if (warp >= NN) return;
    int node = warp;

    float* out = out_scratch ? g_bufA : outp;

    float di = g_dinv[node];
    const float4* selfrow = (const float4*)(hin + (size_t)node * H);
    float ws = di * di;
    float4 v0 = selfrow[lane * 2];
    float4 v1 = selfrow[lane * 2 + 1];
    float a0 = ws * v0.x, a1 = ws * v0.y, a2 = ws * v0.z, a3 = ws * v0.w;
    float a4 = ws * v1.x, a5 = ws * v1.y, a6 = ws * v1.z, a7 = ws * v1.w;

    int beg = g_rowptr[node], end = g_rowptr[node + 1];
    for (int e = beg; e < end; e++) {
        int s = g_csrc[e];
        float w = g_dinv[s] * di;
        const float4* rr = (const float4*)(hin + (size_t)s * H);
        float4 u0 = rr[lane * 2];
        float4 u1 = rr[lane * 2 + 1];
        a0 = fmaf(w, u0.x, a0); a1 = fmaf(w, u0.y, a1);
        a2 = fmaf(w, u0.z, a2); a3 = fmaf(w, u0.w, a3);
        a4 = fmaf(w, u1.x, a4); a5 = fmaf(w, u1.y, a5);
        a6 = fmaf(w, u1.z, a6); a7 = fmaf(w, u1.w, a7);
    }

    const float4* bp = (const float4*)bias;
    float4 b0 = bp[lane * 2];
    float4 b1 = bp[lane * 2 + 1];
    a0 += b0.x; a1 += b0.y; a2 += b0.z; a3 += b0.w;
    a4 += b1.x; a5 += b1.y; a6 += b1.z; a7 += b1.w;
    if (do_relu) {
        a0 = fmaxf(a0, 0.f); a1 = fmaxf(a1, 0.f); a2 = fmaxf(a2, 0.f); a3 = fmaxf(a3, 0.f);
        a4 = fmaxf(a4, 0.f); a5 = fmaxf(a5, 0.f); a6 = fmaxf(a6, 0.f); a7 = fmaxf(a7, 0.f);
    }
    float4* op = (float4*)(out + (size_t)node * H);
    op[lane * 2]     = make_float4(a0, a1, a2, a3);
    op[lane * 2 + 1] = make_float4(a4, a5, a6, a7);
}

// ---------------- launcher ----------------
extern "C" void kernel_launch(void* const* d_in, const int* in_sizes, int n_in,
                              void* d_out, int out_size)
{
    const float* x    = (const float*)d_in[0];
    const void*  ei   = d_in[1];
    const float* prev = (const float*)d_in[2];
    const float* W1   = (const float*)d_in[3];
    const float* b1   = (const float*)d_in[4];
    const float* W2   = (const float*)d_in[5];
    const float* b2   = (const float*)d_in[6];
    const float* gWw  = (const float*)d_in[7];
    const float* gWb  = (const float*)d_in[8];
    const float* gUw  = (const float*)d_in[9];
    const float* gUb  = (const float*)d_in[10];

    int E = in_sizes[1] / 2;

    float* out_lo = (float*)d_out;        // final h_tilde; scratch before that
    float* h_t    = out_lo + NH;          // final h_t

    // graph preprocessing
    detect_kernel<<<1, 256>>>((const int*)ei, E);
    init_kernel<<<(NN + 255) / 256, 256>>>();
    count_kernel<<<(E + 255) / 256, 256>>>(ei, E);
    dinv_kernel<<<(NN + 255) / 256, 256>>>();
    scan_kernel<<<1, 1024>>>();
    scatter_kernel<<<(E + 255) / 256, 256>>>(ei, E);

    // weight images (mat 0=W1, 1=W2, 2=gWw, 3=gUw)
    prep_kernel<<<1024, 256>>>(W1, W2, gWw, gUw);

    dim3 tgrid(2, GM);   // n-halves x m-tiles

    // conv1: h0 = x@W1 -> out_lo (scratch); h = relu(agg(h0)+b1) -> g_bufA
    tgemm_kernel<<<tgrid, 256>>>(x, x, out_lo, b1, b1, NN, 0, 1, 0, 0, 0);
    agg_kernel<<<(NN * 32 + 255) / 256, 256>>>(out_lo, nullptr, b1, 1, 1);

    // conv2: t0 = h@W2 -> out_lo (scratch); h_t = agg(t0)+b2
    tgemm_kernel<<<tgrid, 256>>>(x, x, out_lo, b2, b2, NN, 0, 1, 1, 1, 1);
    agg_kernel<<<(NN * 32 + 255) / 256, 256>>>(out_lo, h_t, b2, 0, 0);

    // gate: acc = h_t@gWw + prev@gUw; out_lo = sig(acc+gWb+gUb)*h_t + (1-sig)*prev
    tgemm_kernel<<<tgrid, 256>>>(h_t, prev, out_lo, gWb, gUb, NN, 1, 2, 2, 3, 0);
}

// round 11
// speedup vs baseline: 1.9673x; 1.0857x over previous
#include <cuda_runtime.h>
#include <cuda_bf16.h>
#include <cuda_fp16.h>
#include <math.h>
#include <stdint.h>

#define NN 50000
#define H 256
#define EMAX 800000
#define NH (NN * H)

#define TILEM 128
#define GM ((NN + TILEM - 1) / TILEM)   // 391

// ---------------- device scratch ----------------
__device__ int   g_is64;
__device__ int   g_deg[NN];
__device__ float g_dinv[NN];
__device__ int   g_rowptr[NN + 1];
__device__ int   g_cursor[NN];
__device__ int   g_csrc[EMAX];
__device__ float g_bufA[NH];                        // h = relu(conv1 agg), fp32
__device__ __align__(16) __half g_h16[NH];          // fp16 GEMM output (agg input)
__device__ __align__(16) __nv_bfloat16 g_Whi[4][65536];  // W^T bf16-hi, [n][k]
__device__ __align__(16) __nv_bfloat16 g_Wlo[4][65536];  // W^T bf16-lo, [n][k]

// mma.sync bf16: D = A(16x16,row) * B(16x8,col) + D, fp32 acc. sm_80+ baseline.
#define MMA_BF16(c, a, b) \
    asm volatile("mma.sync.aligned.m16n8k16.row.col.f32.bf16.bf16.f32 " \
        "{%0,%1,%2,%3}, {%4,%5,%6,%7}, {%8,%9}, {%0,%1,%2,%3};" \
        : "+f"((c)[0]), "+f"((c)[1]), "+f"((c)[2]), "+f"((c)[3]) \
        : "r"((a)[0]), "r"((a)[1]), "r"((a)[2]), "r"((a)[3]), \
          "r"((b)[0]), "r"((b)[1]))

// ---------------- edge dtype detection + graph preprocessing ----------------
__device__ __forceinline__ int load_idx(const void* ei, long long j, int is64) {
    if (is64) return (int)((const long long*)ei)[j];
    return ((const int*)ei)[j];
}

__global__ void detect_kernel(const int* __restrict__ w, int E) {
    __shared__ int nz;
    if (threadIdx.x == 0) nz = 0;
    __syncthreads();
    if (E > 0) {
        for (int j = threadIdx.x; j < 2048; j += blockDim.x) {
            long long idx = ((long long)j * E) / 2048;
            if (w[2 * idx + 1] != 0) atomicOr(&nz, 1);
        }
    }
    __syncthreads();
    if (threadIdx.x == 0) g_is64 = (nz == 0) ? 1 : 0;
}

__global__ void init_kernel() {
    int i = blockIdx.x * blockDim.x + threadIdx.x;
    if (i < NN) { g_deg[i] = 1; g_cursor[i] = 0; }
}

__global__ void count_kernel(const void* __restrict__ ei, int E) {
    int e = blockIdx.x * blockDim.x + threadIdx.x;
    if (e < E) {
        int d = load_idx(ei, (long long)E + e, g_is64);
        if ((unsigned)d < (unsigned)NN) atomicAdd(&g_deg[d], 1);
    }
}

__global__ void dinv_kernel() {
    int i = blockIdx.x * blockDim.x + threadIdx.x;
    if (i < NN) g_dinv[i] = rsqrtf((float)g_deg[i]);
}

__global__ void scan_kernel() {
    __shared__ int sums[1024];
    int t = threadIdx.x;
    const int chunk = (NN + 1023) / 1024;
    int start = t * chunk;
    int end = start + chunk; if (end > NN) end = NN;
    int s = 0;
    for (int i = start; i < end; i++) s += g_deg[i] - 1;
    sums[t] = s;
    __syncthreads();
    if (t == 0) {
        int run = 0;
        for (int i = 0; i < 1024; i++) { int v = sums[i]; sums[i] = run; run += v; }
    }
    __syncthreads();
    int run = sums[t];
    for (int i = start; i < end; i++) {
        run += g_deg[i] - 1;
        g_rowptr[i + 1] = run;
    }
    if (t == 0) g_rowptr[0] = 0;
}

__global__ void scatter_kernel(const void* __restrict__ ei, int E) {
    int e = blockIdx.x * blockDim.x + threadIdx.x;
    if (e < E) {
        int is64 = g_is64;
        int s = load_idx(ei, e, is64);
        int d = load_idx(ei, (long long)E + e, is64);
        if ((unsigned)d < (unsigned)NN && (unsigned)s < (unsigned)NN) {
            int pos = atomicAdd(&g_cursor[d], 1);
            int slot = g_rowptr[d] + pos;
            if (slot < EMAX) g_csrc[slot] = s;
        }
    }
}

// ---------------- weight prep: W -> W^T bf16 hi/lo images ([n][k]) ----------
__global__ void prep_kernel(const float* __restrict__ W1, const float* __restrict__ W2,
                            const float* __restrict__ W3, const float* __restrict__ W4) {
    int idx = blockIdx.x * blockDim.x + threadIdx.x;
    if (idx >= 4 * 65536) return;
    int mat = idx >> 16;
    int rem = idx & 65535;
    int k = rem >> 8;      // input dim
    int n = rem & 255;     // output dim
    const float* W = (mat == 0) ? W1 : (mat == 1) ? W2 : (mat == 2) ? W3 : W4;
    float v = W[k * 256 + n];
    __nv_bfloat16 hi = __float2bfloat16(v);
    __nv_bfloat16 lo = __float2bfloat16(v - __bfloat162float(hi));
    g_Whi[mat][n * 256 + k] = hi;
    g_Wlo[mat][n * 256 + k] = lo;
}

// ---------------- tensor GEMM via mma.sync (split bf16, 3 terms) ------------
// C[M,256] = sum_pairs A_p @ W_p.  CTA tile 128(m) x 128(n), BK=32, 8 warps.
// mode 0: C(fp32) = acc
// mode 1 (gate): a = sigmoid(acc + b1[n] + b2[n]); C = a*A1 + (1-a)*A2
// mode 2: g_h16(fp16) = acc
__global__ __launch_bounds__(256) void tgemm_kernel(
    const float* __restrict__ A1, const float* __restrict__ A2,
    float* __restrict__ C,
    const float* __restrict__ bias1, const float* __restrict__ bias2,
    int M, int mode, int npair, int mat1, int mat2, int a1_scratch)
{
    __shared__ uint32_t sAhi[128][20], sAlo[128][20];
    __shared__ uint32_t sBhi[128][20], sBlo[128][20];

    if (a1_scratch) A1 = g_bufA;

    int tid = threadIdx.x;
    int lane = tid & 31, wid = tid >> 5;
    int g = lane >> 2, tig = lane & 3;
    int warp_m = wid & 3;        // 4 warps over 128 m-rows (32 each)
    int warp_n = wid >> 2;       // 2 warps over 128 n-cols (64 each)
    int m0 = blockIdx.y * TILEM;
    int n0 = blockIdx.x * 128;

    float acc[16][4];
#pragma unroll
    for (int i = 0; i < 16; i++)
#pragma unroll
        for (int j = 0; j < 4; j++) acc[i][j] = 0.f;

    int r = tid >> 1, half = tid & 1;    // A stage-load assignment
    int m_ld = m0 + r;

    for (int pair = 0; pair < npair; pair++) {
        const float* A = pair ? A2 : A1;
        const __nv_bfloat16* Whi = g_Whi[pair ? mat2 : mat1];
        const __nv_bfloat16* Wlo = g_Wlo[pair ? mat2 : mat1];

        for (int k0 = 0; k0 < H; k0 += 32) {
            __syncthreads();   // previous stage fully consumed
            // A stage: 128 rows x 32 k fp32 -> bf16 hi/lo
            {
                const float* arow = A + (size_t)m_ld * H + k0 + half * 16;
#pragma unroll
                for (int w = 0; w < 8; w++) {
                    float2 v = (m_ld < M) ? *(const float2*)(arow + w * 2)
                                          : make_float2(0.f, 0.f);
                    __nv_bfloat16 h0 = __float2bfloat16(v.x);
                    __nv_bfloat16 h1 = __float2bfloat16(v.y);
                    __nv_bfloat16 l0 = __float2bfloat16(v.x - __bfloat162float(h0));
                    __nv_bfloat16 l1 = __float2bfloat16(v.y - __bfloat162float(h1));
                    sAhi[r][half * 8 + w] =
                        (uint32_t)__bfloat16_as_ushort(h0) | ((uint32_t)__bfloat16_as_ushort(h1) << 16);
                    sAlo[r][half * 8 + w] =
                        (uint32_t)__bfloat16_as_ushort(l0) | ((uint32_t)__bfloat16_as_ushort(l1) << 16);
                }
            }
            // B stage: rows n0..n0+127 of W^T, 32 k bf16 (hi+lo), raw copies
#pragma unroll
            for (int l = 0; l < 2; l++) {
                int i = tid * 2 + l;
                int nrow = i >> 2, seg = i & 3;
                size_t off = (size_t)(n0 + nrow) * H + k0 + seg * 8;
                *(uint4*)&sBhi[nrow][seg * 4] = *(const uint4*)(Whi + off);
                *(uint4*)&sBlo[nrow][seg * 4] = *(const uint4*)(Wlo + off);
            }
            __syncthreads();

            // compute: 2 k16 steps
#pragma unroll
            for (int ks = 0; ks < 2; ks++) {
                int kw = ks * 8;
                uint32_t ah[2][4], al[2][4], bh[8][2], bl[8][2];
#pragma unroll
                for (int mt = 0; mt < 2; mt++) {
                    int r0 = warp_m * 32 + mt * 16 + g;
                    ah[mt][0] = sAhi[r0][kw + tig];
                    ah[mt][1] = sAhi[r0 + 8][kw + tig];
                    ah[mt][2] = sAhi[r0][kw + tig + 4];
                    ah[mt][3] = sAhi[r0 + 8][kw + tig + 4];
                    al[mt][0] = sAlo[r0][kw + tig];
                    al[mt][1] = sAlo[r0 + 8][kw + tig];
                    al[mt][2] = sAlo[r0][kw + tig + 4];
                    al[mt][3] = sAlo[r0 + 8][kw + tig + 4];
                }
#pragma unroll
                for (int nt = 0; nt < 8; nt++) {
                    int n = warp_n * 64 + nt * 8 + g;
                    bh[nt][0] = sBhi[n][kw + tig];
                    bh[nt][1] = sBhi[n][kw + tig + 4];
                    bl[nt][0] = sBlo[n][kw + tig];
                    bl[nt][1] = sBlo[n][kw + tig + 4];
                }
#pragma unroll
                for (int mt = 0; mt < 2; mt++)
#pragma unroll
                    for (int nt = 0; nt < 8; nt++) {
                        float* c = acc[mt * 8 + nt];
                        MMA_BF16(c, ah[mt], bh[nt]);
                        MMA_BF16(c, al[mt], bh[nt]);
                        MMA_BF16(c, ah[mt], bl[nt]);
                    }
            }
        }
    }

    // epilogue
#pragma unroll
    for (int mt = 0; mt < 2; mt++) {
        int r0 = m0 + warp_m * 32 + mt * 16 + g;
#pragma unroll
        for (int nt = 0; nt < 8; nt++) {
            int ncol = n0 + warp_n * 64 + nt * 8 + tig * 2;
            float* c = acc[mt * 8 + nt];
            if (mode == 0) {
                if (r0 < M)
                    *(float2*)(C + (size_t)r0 * H + ncol) = make_float2(c[0], c[1]);
                if (r0 + 8 < M)
                    *(float2*)(C + (size_t)(r0 + 8) * H + ncol) = make_float2(c[2], c[3]);
            } else if (mode == 2) {
                if (r0 < M)
                    *(__half2*)(g_h16 + (size_t)r0 * H + ncol) = __floats2half2_rn(c[0], c[1]);
                if (r0 + 8 < M)
                    *(__half2*)(g_h16 + (size_t)(r0 + 8) * H + ncol) = __floats2half2_rn(c[2], c[3]);
            } else {
                float bs0 = bias1[ncol] + bias2[ncol];
                float bs1 = bias1[ncol + 1] + bias2[ncol + 1];
#pragma unroll
                for (int rr = 0; rr < 2; rr++) {
                    int m = r0 + rr * 8;
                    if (m < M) {
                        float2 ht = *(const float2*)(A1 + (size_t)m * H + ncol);
                        float2 pv = *(const float2*)(A2 + (size_t)m * H + ncol);
                        float g0 = c[rr * 2 + 0] + bs0;
                        float g1 = c[rr * 2 + 1] + bs1;
                        float a0 = 1.f / (1.f + __expf(-g0));
                        float a1 = 1.f / (1.f + __expf(-g1));
                        float2 o;
                        o.x = fmaf(a0, ht.x - pv.x, pv.x);
                        o.y = fmaf(a1, ht.y - pv.y, pv.y);
                        *(float2*)(C + (size_t)m * H + ncol) = o;
                    }
                }
            }
        }
    }
}

// ---------------- aggregation: one warp per node, fp16 gather ---------------
// reads g_h16 (fp16 messages); accumulates fp32; writes fp32.
__global__ void agg_kernel(float* outp, const float* __restrict__ bias,
                           int do_relu, int out_scratch)
{
    int warp = (blockIdx.x * blockDim.x + threadIdx.x) >> 5;
    int lane = threadIdx.x & 31;
    if (warp >= NN) return;
    int node = warp;

    float* out = out_scratch ? g_bufA : outp;

    float di = g_dinv[node];
    float ws = di * di;

    // lane handles 8 contiguous values: one uint4 = 8 fp16
    const uint4* selfrow = (const uint4*)(g_h16 + (size_t)node * H);
    uint4 sv = selfrow[lane];
    const __half2* sh = (const __half2*)&sv;
    float2 f0 = __half22float2(sh[0]);
    float2 f1 = __half22float2(sh[1]);
    float2 f2 = __half22float2(sh[2]);
    float2 f3 = __half22float2(sh[3]);
    float a0 = ws * f0.x, a1 = ws * f0.y, a2 = ws * f1.x, a3 = ws * f1.y;
    float a4 = ws * f2.x, a5 = ws * f2.y, a6 = ws * f3.x, a7 = ws * f3.y;

    int beg = g_rowptr[node], end = g_rowptr[node + 1];
    for (int e = beg; e < end; e++) {
        int s = g_csrc[e];
        float w = g_dinv[s] * di;
        uint4 u = ((const uint4*)(g_h16 + (size_t)s * H))[lane];
        const __half2* hp = (const __half2*)&u;
        float2 u0 = __half22float2(hp[0]);
        float2 u1 = __half22float2(hp[1]);
        float2 u2 = __half22float2(hp[2]);
        float2 u3 = __half22float2(hp[3]);
        a0 = fmaf(w, u0.x, a0); a1 = fmaf(w, u0.y, a1);
        a2 = fmaf(w, u1.x, a2); a3 = fmaf(w, u1.y, a3);
        a4 = fmaf(w, u2.x, a4); a5 = fmaf(w, u2.y, a5);
        a6 = fmaf(w, u3.x, a6); a7 = fmaf(w, u3.y, a7);
    }

    const float4* bp = (const float4*)bias;
    float4 b0 = bp[lane * 2];
    float4 b1 = bp[lane * 2 + 1];
    a0 += b0.x; a1 += b0.y; a2 += b0.z; a3 += b0.w;
    a4 += b1.x; a5 += b1.y; a6 += b1.z; a7 += b1.w;
    if (do_relu) {
        a0 = fmaxf(a0, 0.f); a1 = fmaxf(a1, 0.f); a2 = fmaxf(a2, 0.f); a3 = fmaxf(a3, 0.f);
        a4 = fmaxf(a4, 0.f); a5 = fmaxf(a5, 0.f); a6 = fmaxf(a6, 0.f); a7 = fmaxf(a7, 0.f);
    }
    float4* op = (float4*)(out + (size_t)node * H);
    op[lane * 2]     = make_float4(a0, a1, a2, a3);
    op[lane * 2 + 1] = make_float4(a4, a5, a6, a7);
}

// ---------------- launcher ----------------
extern "C" void kernel_launch(void* const* d_in, const int* in_sizes, int n_in,
                              void* d_out, int out_size)
{
    const float* x    = (const float*)d_in[0];
    const void*  ei   = d_in[1];
    const float* prev = (const float*)d_in[2];
    const float* W1   = (const float*)d_in[3];
    const float* b1   = (const float*)d_in[4];
    const float* W2   = (const float*)d_in[5];
    const float* b2   = (const float*)d_in[6];
    const float* gWw  = (const float*)d_in[7];
    const float* gWb  = (const float*)d_in[8];
    const float* gUw  = (const float*)d_in[9];
    const float* gUb  = (const float*)d_in[10];

    int E = in_sizes[1] / 2;

    float* out_lo = (float*)d_out;        // final h_tilde
    float* h_t    = out_lo + NH;          // final h_t

    // graph preprocessing
    detect_kernel<<<1, 256>>>((const int*)ei, E);
    init_kernel<<<(NN + 255) / 256, 256>>>();
    count_kernel<<<(E + 255) / 256, 256>>>(ei, E);
    dinv_kernel<<<(NN + 255) / 256, 256>>>();
    scan_kernel<<<1, 1024>>>();
    scatter_kernel<<<(E + 255) / 256, 256>>>(ei, E);

    // weight images (mat 0=W1, 1=W2, 2=gWw, 3=gUw)
    prep_kernel<<<1024, 256>>>(W1, W2, gWw, gUw);

    dim3 tgrid(2, GM);   // n-halves x m-tiles

    // conv1: h0 = x@W1 -> g_h16 (fp16); h = relu(agg+b1) -> g_bufA (fp32)
    tgemm_kernel<<<tgrid, 256>>>(x, x, nullptr, b1, b1, NN, 2, 1, 0, 0, 0);
    agg_kernel<<<(NN * 32 + 255) / 256, 256>>>(nullptr, b1, 1, 1);

    // conv2: t0 = h@W2 -> g_h16 (fp16); h_t = agg+b2 -> out_hi (fp32)
    tgemm_kernel<<<tgrid, 256>>>(x, x, nullptr, b2, b2, NN, 2, 1, 1, 1, 1);
    agg_kernel<<<(NN * 32 + 255) / 256, 256>>>(h_t, b2, 0, 0);

    // gate: acc = h_t@gWw + prev@gUw; out_lo = sig(acc+gWb+gUb)*h_t + (1-sig)*prev
    tgemm_kernel<<<tgrid, 256>>>(h_t, prev, out_lo, gWb, gUb, NN, 1, 2, 2, 3, 0);
}